// round 12
// baseline (speedup 1.0000x reference)
#include <cuda_runtime.h>
#include <cuda_fp16.h>
#include <cstdint>

// ===================== problem sizes =====================
static constexpr int  B_   = 8192;
static constexpr int  C_   = 12;
static constexpr int  A_   = 8;
static constexpr int  DI   = 1024;
static constexpr int  DO   = 1024;
static constexpr int  NTOT = C_ * DO;        // 12288
static constexpr long NX   = (long)B_ * DI;      // 8388608
static constexpr long NW   = (long)NTOT * DI;    // 12582912
static constexpr float S_   = 64.f;              // mixing scale s
static constexpr float CMAIN = 1.f - 1.f / 64.f; // u = CMAIN*main + mix

// ===================== device scratch (no allocs allowed) ====================
// Row layout (2048 halves = 4096 bytes):
//   g_x[b] = [ xh | a2 ],  a2 = fp16(xh + s*xl)
//   g_w[n] = [ wh | b2 ],  b2 = fp16(wl + wh/s)
__device__ __half g_x[(size_t)B_ * 2 * DI];      // 33 MB
__device__ __half g_w[(size_t)NTOT * 2 * DI];    // 50 MB
__device__ float  g_u[(size_t)B_ * NTOT];        // 402 MB
__device__ float  g_ent[B_];

// ===================== helpers =====================
__device__ __forceinline__ uint32_t smem_u32(const void* p) {
    uint32_t a;
    asm("{ .reg .u64 t; cvta.to.shared.u64 t, %1; cvt.u32.u64 %0, t; }" : "=r"(a) : "l"(p));
    return a;
}
__device__ __forceinline__ void cp_async16(uint32_t smem_dst, const void* gsrc) {
    asm volatile("cp.async.cg.shared.global [%0], [%1], 16;" :: "r"(smem_dst), "l"(gsrc));
}
#define CP_COMMIT() asm volatile("cp.async.commit_group;" ::: "memory")
#define CP_WAIT(n)  asm volatile("cp.async.wait_group %0;" :: "n"(n) : "memory")

#define LDSM_X4(R0,R1,R2,R3,ADDR) \
    asm volatile("ldmatrix.sync.aligned.m8n8.x4.shared.b16 {%0,%1,%2,%3}, [%4];" \
                 : "=r"(R0),"=r"(R1),"=r"(R2),"=r"(R3) : "r"(ADDR))

#define MMA16816(C0,C1,C2,C3,A0,A1,A2,A3,B0,B1) \
    asm volatile("mma.sync.aligned.m16n8k16.row.col.f32.f16.f16.f32 " \
                 "{%0,%1,%2,%3}, {%4,%5,%6,%7}, {%8,%9}, {%0,%1,%2,%3};" \
                 : "+f"(C0),"+f"(C1),"+f"(C2),"+f"(C3) \
                 : "r"(A0),"r"(A1),"r"(A2),"r"(A3),"r"(B0),"r"(B1))

// ===================== kernel 1: split (float4-vectorized) =====================
// one thread handles 4 consecutive k positions of one row
__global__ __launch_bounds__(256) void split_kernel(const float* __restrict__ x,
                                                    const float* __restrict__ W) {
    long q = (long)blockIdx.x * 256 + threadIdx.x;   // quad index
    const long NXQ = NX >> 2;                        // 2097152
    if (q < NXQ) {
        long b = q >> 8, kq = (q & 255) * 4;
        float4 v = *(const float4*)(x + (b << 10) + kq);
        __half2 h01 = __floats2half2_rn(v.x, v.y);
        __half2 h23 = __floats2half2_rn(v.z, v.w);
        float2 hf01 = __half22float2(h01), hf23 = __half22float2(h23);
        __half2 a01 = __floats2half2_rn(hf01.x + S_ * (v.x - hf01.x),
                                        hf01.y + S_ * (v.y - hf01.y));
        __half2 a23 = __floats2half2_rn(hf23.x + S_ * (v.z - hf23.x),
                                        hf23.y + S_ * (v.w - hf23.y));
        size_t base = (size_t)b * 2048 + kq;
        *(__half2*)(g_x + base)          = h01;
        *(__half2*)(g_x + base + 2)      = h23;
        *(__half2*)(g_x + base + 1024)   = a01;
        *(__half2*)(g_x + base + 1026)   = a23;
    } else {
        long j = q - NXQ;
        if (j < (NW >> 2)) {
            long n = j >> 8, kq = (j & 255) * 4;
            float4 v = *(const float4*)(W + (n << 10) + kq);
            __half2 h01 = __floats2half2_rn(v.x, v.y);
            __half2 h23 = __floats2half2_rn(v.z, v.w);
            float2 hf01 = __half22float2(h01), hf23 = __half22float2(h23);
            __half2 b01 = __floats2half2_rn((v.x - hf01.x) + hf01.x * (1.f / S_),
                                            (v.y - hf01.y) + hf01.y * (1.f / S_));
            __half2 b23 = __floats2half2_rn((v.z - hf23.x) + hf23.x * (1.f / S_),
                                            (v.w - hf23.y) + hf23.y * (1.f / S_));
            size_t base = (size_t)n * 2048 + kq;
            *(__half2*)(g_w + base)          = h01;
            *(__half2*)(g_w + base + 2)      = h23;
            *(__half2*)(g_w + base + 1024)   = b01;
            *(__half2*)(g_w + base + 1026)   = b23;
        }
    }
}

// ===================== kernel 2: persistent HMMA GEMM =========================
// grid = 148 persistent CTAs; each walks tiles cta, cta+148, ... of 3072.
// Continuous cross-tile cp.async pipeline: load cursor runs STAGES-1 global
// iters ahead of compute cursor, so next tile's data streams in during the
// current tile's epilogue. Tile (48 n) x (64 m), CTA 128x256, 64 k-iters.
static constexpr int TM = 128, TN = 256, STAGES = 4;
static constexpr int ROWB = 80;
static constexpr int ASTG = TM * ROWB;            // 10240
static constexpr int BSTG = TN * ROWB;            // 20480
static constexpr int STG  = ASTG + BSTG;          // 30720
static constexpr int GEMM_SMEM = STAGES * STG;    // 122880
static constexpr int KI = 32;                     // main iters (xh.wh)
static constexpr int KT = 64;                     // + 32 mix iters (a2.b2)
static constexpr int NTILE_X = NTOT / TN;         // 48
static constexpr long NTILES = (long)NTILE_X * (B_ / TM);  // 3072
static constexpr int GRID = 148;

__global__ __launch_bounds__(256, 1) void gemm_kernel(const float* __restrict__ bias) {
    extern __shared__ char sm[];
    const uint32_t sb = smem_u32(sm);
    const int tid  = threadIdx.x;
    const int lane = tid & 31;
    const int w    = tid >> 5;
    const int wm   = w & 1;
    const int wn   = w >> 1;
    const int cta  = blockIdx.x;

    // ldmatrix per-lane bases
    const uint32_t rowA = (uint32_t)(wm * 64 + (lane & 7) + ((lane >> 3) & 1) * 8);
    const uint32_t colA = (uint32_t)(((lane >> 4) & 1) * 16);
    const uint32_t rowB = (uint32_t)(wn * 64 + (lane & 7) + ((lane >> 4) & 1) * 8);
    const uint32_t colB = (uint32_t)(((lane >> 3) & 1) * 16);

    const char* cx = (const char*)g_x;
    const char* cw = (const char*)g_w;

    // global-iter load: g -> (local tile lt = g/64, k-iter j = g%64)
    auto load_stage_g = [&](long g) {
        const long lt = g >> 6;
        const long tile = cta + lt * GRID;
        if (tile >= NTILES) return;        // caller still commits (empty group)
        const int  jj = (int)(g & 63);
        const long m0l = (tile / NTILE_X) * TM;
        const long n0l = (tile % NTILE_X) * TN;
        const uint32_t As = sb + (uint32_t)((g & 3) * STG);
        const uint32_t Bs = As + ASTG;
        const int kb = jj * 64;
        #pragma unroll
        for (int it = 0; it < 2; it++) {
            int idx = tid + it * 256;             // < 512
            int r = idx >> 2, c = idx & 3;
            cp_async16(As + r * ROWB + c * 16, cx + (size_t)(m0l + r) * 4096 + kb + c * 16);
        }
        #pragma unroll
        for (int it = 0; it < 4; it++) {
            int idx = tid + it * 256;             // < 1024
            int r = idx >> 2, c = idx & 3;
            cp_async16(Bs + r * ROWB + c * 16, cw + (size_t)(n0l + r) * 4096 + kb + c * 16);
        }
    };

    long gload = 0;
    #pragma unroll
    for (int s = 0; s < STAGES - 1; s++) { load_stage_g(gload); CP_COMMIT(); gload++; }

    long gcomp = 0;
    #pragma unroll 1
    for (long tile = cta; tile < NTILES; tile += GRID) {
        const long m0 = (tile / NTILE_X) * TM;
        const long n0 = (tile % NTILE_X) * TN;

        float acc[4][8][4];
        #pragma unroll
        for (int mt = 0; mt < 4; mt++)
            #pragma unroll
            for (int nt = 0; nt < 8; nt++)
                #pragma unroll
                for (int e = 0; e < 4; e++) acc[mt][nt][e] = 0.f;

        #pragma unroll 1
        for (int i = 0; i < KT; i++, gcomp++, gload++) {
            if (i == KI) {
                // u = (1 - 1/s)*main + mix  (exact mid-tile rescale)
                #pragma unroll
                for (int mt = 0; mt < 4; mt++)
                    #pragma unroll
                    for (int nt = 0; nt < 8; nt++)
                        #pragma unroll
                        for (int e = 0; e < 4; e++)
                            acc[mt][nt][e] *= CMAIN;
            }
            CP_WAIT(STAGES - 2);
            __syncthreads();
            load_stage_g(gload);
            CP_COMMIT();
            const uint32_t As = sb + (uint32_t)((gcomp & 3) * STG);
            const uint32_t Bs = As + ASTG;
            #pragma unroll
            for (int ks = 0; ks < 2; ks++) {
                uint32_t a[4][4], b[8][2];
                #pragma unroll
                for (int mt = 0; mt < 4; mt++) {
                    uint32_t ad = As + (rowA + mt * 16) * ROWB + ks * 32 + colA;
                    LDSM_X4(a[mt][0], a[mt][1], a[mt][2], a[mt][3], ad);
                }
                #pragma unroll
                for (int p = 0; p < 4; p++) {
                    uint32_t bd = Bs + (rowB + p * 16) * ROWB + ks * 32 + colB;
                    LDSM_X4(b[2*p][0], b[2*p][1], b[2*p+1][0], b[2*p+1][1], bd);
                }
                #pragma unroll
                for (int mt = 0; mt < 4; mt++)
                    #pragma unroll
                    for (int nt = 0; nt < 8; nt++)
                        MMA16816(acc[mt][nt][0], acc[mt][nt][1], acc[mt][nt][2], acc[mt][nt][3],
                                 a[mt][0], a[mt][1], a[mt][2], a[mt][3],
                                 b[nt][0], b[nt][1]);
            }
        }

        // epilogue: add bias, store fp32 to g_u (regs/gmem only; loads for the
        // next tile are already streaming into smem behind us)
        #pragma unroll
        for (int nt = 0; nt < 8; nt++) {
            const long n = n0 + wn * 64 + nt * 8 + 2 * (lane & 3);
            const float2 bz = *(const float2*)&bias[n];
            #pragma unroll
            for (int mt = 0; mt < 4; mt++) {
                const long m = m0 + wm * 64 + mt * 16 + (lane >> 2);
                float2 lo = { acc[mt][nt][0] + bz.x, acc[mt][nt][1] + bz.y };
                float2 hi = { acc[mt][nt][2] + bz.x, acc[mt][nt][3] + bz.y };
                *(float2*)&g_u[(size_t)m * NTOT + n]       = lo;
                *(float2*)&g_u[(size_t)(m + 8) * NTOT + n] = hi;
            }
        }
    }
}

// ===================== kernel 3: fused routing =====================
__device__ __forceinline__ float block_sum(float v, volatile float* smr) {
    int lane = threadIdx.x & 31, w = threadIdx.x >> 5;
    #pragma unroll
    for (int o = 16; o; o >>= 1) v += __shfl_xor_sync(0xffffffffu, v, o);
    if (lane == 0) smr[w] = v;
    __syncthreads();
    if (threadIdx.x == 0) {
        float s = smr[0];
        #pragma unroll
        for (int i = 1; i < 8; i++) s += smr[i];
        smr[8] = s;
    }
    __syncthreads();
    float r = smr[8];
    __syncthreads();
    return r;
}
__device__ __forceinline__ float block_max(float v, volatile float* smr) {
    int lane = threadIdx.x & 31, w = threadIdx.x >> 5;
    #pragma unroll
    for (int o = 16; o; o >>= 1) v = fmaxf(v, __shfl_xor_sync(0xffffffffu, v, o));
    if (lane == 0) smr[w] = v;
    __syncthreads();
    if (threadIdx.x == 0) {
        float s = smr[0];
        #pragma unroll
        for (int i = 1; i < 8; i++) s = fmaxf(s, smr[i]);
        smr[8] = s;
    }
    __syncthreads();
    float r = smr[8];
    __syncthreads();
    return r;
}

__global__ __launch_bounds__(256) void routing_kernel(float* __restrict__ out) {
    __shared__ float sred[9];
    __shared__ float s12[8 * 12];
    __shared__ float sb12[12];
    const int b = blockIdx.x;
    const int t = threadIdx.x;
    const int lid = t & 31, wid = t >> 5;

    float4 ur[12];
    const float* ub = g_u + (size_t)b * NTOT;
    #pragma unroll
    for (int c = 0; c < 12; c++)
        ur[c] = *(const float4*)(ub + c * 1024 + 4 * t);

    float blog[12];
    #pragma unroll
    for (int c = 0; c < 12; c++) blog[c] = 0.f;

    float4 s4, v4;
    for (int it = 0; it < 3; it++) {
        float mx = blog[0];
        #pragma unroll
        for (int c = 1; c < 12; c++) mx = fmaxf(mx, blog[c]);
        float cc[12], se = 0.f;
        #pragma unroll
        for (int c = 0; c < 12; c++) { cc[c] = expf(blog[c] - mx); se += cc[c]; }
        const float inv = 1.f / se;
        s4 = make_float4(0.f, 0.f, 0.f, 0.f);
        #pragma unroll
        for (int c = 0; c < 12; c++) {
            float wgt = cc[c] * inv;
            s4.x = fmaf(wgt, ur[c].x, s4.x);
            s4.y = fmaf(wgt, ur[c].y, s4.y);
            s4.z = fmaf(wgt, ur[c].z, s4.z);
            s4.w = fmaf(wgt, ur[c].w, s4.w);
        }
        float n2p = s4.x*s4.x + s4.y*s4.y + s4.z*s4.z + s4.w*s4.w;
        float n2 = block_sum(n2p, sred);
        float nrm = sqrtf(n2);
        float scale = n2 / (1.f + n2) / (nrm + 1e-8f);
        v4 = make_float4(scale*s4.x, scale*s4.y, scale*s4.z, scale*s4.w);
        if (it < 2) {
            #pragma unroll
            for (int c = 0; c < 12; c++) {
                float p = ur[c].x*v4.x + ur[c].y*v4.y + ur[c].z*v4.z + ur[c].w*v4.w;
                #pragma unroll
                for (int o = 16; o; o >>= 1) p += __shfl_xor_sync(0xffffffffu, p, o);
                if (lid == 0) s12[wid * 12 + c] = p;
            }
            __syncthreads();
            if (t < 12) {
                float a2 = 0.f;
                #pragma unroll
                for (int w2 = 0; w2 < 8; w2++) a2 += s12[w2 * 12 + t];
                sb12[t] = a2;
            }
            __syncthreads();
            #pragma unroll
            for (int c = 0; c < 12; c++) blog[c] += sb12[c];
            __syncthreads();
        }
    }

    size_t ob = (size_t)b * (A_ * DO) + 4 * t;
    #pragma unroll
    for (int a = 0; a < A_; a++)
        *(float4*)(out + ob + (size_t)a * DO) = v4;

    float mxp = fmaxf(fmaxf(s4.x, s4.y), fmaxf(s4.z, s4.w));
    float mxs = block_max(mxp, sred);
    float e0 = expf(s4.x - mxs), e1 = expf(s4.y - mxs);
    float e2 = expf(s4.z - mxs), e3 = expf(s4.w - mxs);
    float sume = block_sum(e0 + e1 + e2 + e3, sred);
    float denom = sume + 1e-10f;
    float ep = 0.f;
    {
        float p0 = e0 / denom, p1 = e1 / denom, p2 = e2 / denom, p3 = e3 / denom;
        ep += p0 * logf(p0 + 1e-10f) + p1 * logf(p1 + 1e-10f)
            + p2 * logf(p2 + 1e-10f) + p3 * logf(p3 + 1e-10f);
    }
    float H = -block_sum(ep, sred);
    H = fminf(fmaxf(H, 0.f), 10.f);
    if (t == 0) g_ent[b] = H;
}

// ===================== kernel 4: entropy loss scalar =====================
__global__ __launch_bounds__(256) void finalize_kernel(float* __restrict__ out, long idx) {
    __shared__ float sred[9];
    const int t = threadIdx.x;
    float sum = 0.f;
    for (int k = t; k < B_; k += 256) sum += g_ent[k];
    float total = block_sum(sum, sred);
    if (t == 0) {
        float mean = total / (float)B_;
        out[idx] = -0.4f / (1.f + expf(-mean));
    }
}

// ===================== launch =====================
extern "C" void kernel_launch(void* const* d_in, const int* in_sizes, int n_in,
                              void* d_out, int out_size) {
    const float* x    = (const float*)d_in[0];
    const float* W    = (const float*)d_in[1];
    const float* bias = (const float*)d_in[2];
    float* out = (float*)d_out;

    long totalq = (NX + NW) / 4;
    split_kernel<<<(int)((totalq + 255) / 256), 256>>>(x, W);

    (void)cudaFuncSetAttribute(gemm_kernel, cudaFuncAttributeMaxDynamicSharedMemorySize, GEMM_SMEM);
    gemm_kernel<<<GRID, 256, GEMM_SMEM>>>(bias);

    routing_kernel<<<B_, 256>>>(out);
    finalize_kernel<<<1, 256>>>(out, (long)out_size - 1);
}

// round 13
// speedup vs baseline: 1.1641x; 1.1641x over previous
#include <cuda_runtime.h>
#include <cuda_fp16.h>
#include <cstdint>

// ===================== problem sizes =====================
static constexpr int  B_   = 8192;
static constexpr int  C_   = 12;
static constexpr int  A_   = 8;
static constexpr int  DI   = 1024;
static constexpr int  DO   = 1024;
static constexpr int  NTOT = C_ * DO;        // 12288
static constexpr long NX   = (long)B_ * DI;      // 8388608
static constexpr long NW   = (long)NTOT * DI;    // 12582912
static constexpr float S_   = 64.f;              // mixing scale s
static constexpr float CMAIN = 1.f - 1.f / 64.f; // u = CMAIN*main + mix

// ===================== device scratch (no allocs allowed) ====================
// Row layout (2048 halves = 4096 bytes):
//   g_x[b] = [ xh | a2 ],  a2 = fp16(xh + s*xl)
//   g_w[n] = [ wh | b2 ],  b2 = fp16(wl + wh/s)
__device__ __half g_x[(size_t)B_ * 2 * DI];      // 33 MB
__device__ __half g_w[(size_t)NTOT * 2 * DI];    // 50 MB
__device__ float  g_u[(size_t)B_ * NTOT];        // 402 MB
__device__ float  g_ent[B_];

// ===================== helpers =====================
__device__ __forceinline__ uint32_t smem_u32(const void* p) {
    uint32_t a;
    asm("{ .reg .u64 t; cvta.to.shared.u64 t, %1; cvt.u32.u64 %0, t; }" : "=r"(a) : "l"(p));
    return a;
}
__device__ __forceinline__ void cp_async16(uint32_t smem_dst, const void* gsrc) {
    asm volatile("cp.async.cg.shared.global [%0], [%1], 16;" :: "r"(smem_dst), "l"(gsrc));
}
#define CP_COMMIT() asm volatile("cp.async.commit_group;" ::: "memory")
#define CP_WAIT(n)  asm volatile("cp.async.wait_group %0;" :: "n"(n) : "memory")

#define LDSM_X4(R0,R1,R2,R3,ADDR) \
    asm volatile("ldmatrix.sync.aligned.m8n8.x4.shared.b16 {%0,%1,%2,%3}, [%4];" \
                 : "=r"(R0),"=r"(R1),"=r"(R2),"=r"(R3) : "r"(ADDR))

#define MMA16816(C0,C1,C2,C3,A0,A1,A2,A3,B0,B1) \
    asm volatile("mma.sync.aligned.m16n8k16.row.col.f32.f16.f16.f32 " \
                 "{%0,%1,%2,%3}, {%4,%5,%6,%7}, {%8,%9}, {%0,%1,%2,%3};" \
                 : "+f"(C0),"+f"(C1),"+f"(C2),"+f"(C3) \
                 : "r"(A0),"r"(A1),"r"(A2),"r"(A3),"r"(B0),"r"(B1))

// ===================== kernel 1: split (float4-vectorized) =====================
__global__ __launch_bounds__(256) void split_kernel(const float* __restrict__ x,
                                                    const float* __restrict__ W) {
    long q = (long)blockIdx.x * 256 + threadIdx.x;   // quad index
    const long NXQ = NX >> 2;                        // 2097152
    if (q < NXQ) {
        long b = q >> 8, kq = (q & 255) * 4;
        float4 v = *(const float4*)(x + (b << 10) + kq);
        __half2 h01 = __floats2half2_rn(v.x, v.y);
        __half2 h23 = __floats2half2_rn(v.z, v.w);
        float2 hf01 = __half22float2(h01), hf23 = __half22float2(h23);
        __half2 a01 = __floats2half2_rn(hf01.x + S_ * (v.x - hf01.x),
                                        hf01.y + S_ * (v.y - hf01.y));
        __half2 a23 = __floats2half2_rn(hf23.x + S_ * (v.z - hf23.x),
                                        hf23.y + S_ * (v.w - hf23.y));
        size_t base = (size_t)b * 2048 + kq;
        *(__half2*)(g_x + base)          = h01;
        *(__half2*)(g_x + base + 2)      = h23;
        *(__half2*)(g_x + base + 1024)   = a01;
        *(__half2*)(g_x + base + 1026)   = a23;
    } else {
        long j = q - NXQ;
        if (j < (NW >> 2)) {
            long n = j >> 8, kq = (j & 255) * 4;
            float4 v = *(const float4*)(W + (n << 10) + kq);
            __half2 h01 = __floats2half2_rn(v.x, v.y);
            __half2 h23 = __floats2half2_rn(v.z, v.w);
            float2 hf01 = __half22float2(h01), hf23 = __half22float2(h23);
            __half2 b01 = __floats2half2_rn((v.x - hf01.x) + hf01.x * (1.f / S_),
                                            (v.y - hf01.y) + hf01.y * (1.f / S_));
            __half2 b23 = __floats2half2_rn((v.z - hf23.x) + hf23.x * (1.f / S_),
                                            (v.w - hf23.y) + hf23.y * (1.f / S_));
            size_t base = (size_t)n * 2048 + kq;
            *(__half2*)(g_w + base)          = h01;
            *(__half2*)(g_w + base + 2)      = h23;
            *(__half2*)(g_w + base + 1024)   = b01;
            *(__half2*)(g_w + base + 1026)   = b23;
        }
    }
}

// ===================== kernel 2: HMMA GEMM, 2 CTAs/SM ==========================
// CTA 128x128, 8 warps (2m x 4n) of 64x32, 64B data rows (+16B pad = 80B
// stride, conflict-free ldmatrix), 4-stage cp.async pipeline, 64 k-iters.
// smem 80KB/CTA and <=128 regs -> 2 CTAs resident per SM: sibling CTA's MMA
// issue covers this CTA's sync/prologue/epilogue bubbles.
static constexpr int TM = 128, TN = 128, STAGES = 4;
static constexpr int ROWB = 80;
static constexpr int ASTG = TM * ROWB;            // 10240
static constexpr int BSTG = TN * ROWB;            // 10240
static constexpr int STG  = ASTG + BSTG;          // 20480
static constexpr int GEMM_SMEM = STAGES * STG;    // 81920
static constexpr int KI = 32;                     // main iters (xh.wh)
static constexpr int KT = 64;                     // + 32 mix iters (a2.b2)

__global__ __launch_bounds__(256, 2) void gemm_kernel(const float* __restrict__ bias) {
    extern __shared__ char sm[];
    const uint32_t sb = smem_u32(sm);
    const int tid  = threadIdx.x;
    const int lane = tid & 31;
    const int w    = tid >> 5;
    const int wm   = w & 1;          // 2 warps along M (64 each)
    const int wn   = w >> 1;         // 4 warps along N (32 each)
    const long m0  = (long)blockIdx.y * TM;
    const long n0  = (long)blockIdx.x * TN;

    float acc[4][4][4];
    #pragma unroll
    for (int mt = 0; mt < 4; mt++)
        #pragma unroll
        for (int nt = 0; nt < 4; nt++)
            #pragma unroll
            for (int e = 0; e < 4; e++) acc[mt][nt][e] = 0.f;

    // ldmatrix per-lane bases
    const uint32_t rowA = (uint32_t)(wm * 64 + (lane & 7) + ((lane >> 3) & 1) * 8);
    const uint32_t colA = (uint32_t)(((lane >> 4) & 1) * 16);
    const uint32_t rowB = (uint32_t)(wn * 32 + (lane & 7) + ((lane >> 4) & 1) * 8);
    const uint32_t colB = (uint32_t)(((lane >> 3) & 1) * 16);

    const char* cx = (const char*)g_x;
    const char* cw = (const char*)g_w;

    // per-iter row = 64 data bytes = 4x16B granules; A 512 granules, B 512.
    auto load_stage = [&](int j) {
        const uint32_t As = sb + (uint32_t)((j & 3) * STG);
        const uint32_t Bs = As + ASTG;
        const int kb = j * 64;   // byte offset within 4096-byte row [xh|a2]/[wh|b2]
        #pragma unroll
        for (int it = 0; it < 2; it++) {
            int idx = tid + it * 256;             // < 512
            int r = idx >> 2, c = idx & 3;
            cp_async16(As + r * ROWB + c * 16, cx + (size_t)(m0 + r) * 4096 + kb + c * 16);
        }
        #pragma unroll
        for (int it = 0; it < 2; it++) {
            int idx = tid + it * 256;             // < 512
            int r = idx >> 2, c = idx & 3;
            cp_async16(Bs + r * ROWB + c * 16, cw + (size_t)(n0 + r) * 4096 + kb + c * 16);
        }
    };

    #pragma unroll
    for (int j = 0; j < STAGES - 1; j++) { load_stage(j); CP_COMMIT(); }

    #pragma unroll 1
    for (int i = 0; i < KT; i++) {
        if (i == KI) {
            // u = (1 - 1/s)*main + mix  (exact phase-boundary rescale)
            #pragma unroll
            for (int mt = 0; mt < 4; mt++)
                #pragma unroll
                for (int nt = 0; nt < 4; nt++)
                    #pragma unroll
                    for (int e = 0; e < 4; e++)
                        acc[mt][nt][e] *= CMAIN;
        }
        CP_WAIT(STAGES - 2);
        __syncthreads();
        if (i + STAGES - 1 < KT) load_stage(i + STAGES - 1);
        CP_COMMIT();

        const uint32_t As = sb + (uint32_t)((i & 3) * STG);
        const uint32_t Bs = As + ASTG;
        #pragma unroll
        for (int ks = 0; ks < 2; ks++) {
            uint32_t a[4][4], b[4][2];
            #pragma unroll
            for (int mt = 0; mt < 4; mt++) {
                uint32_t ad = As + (rowA + mt * 16) * ROWB + ks * 32 + colA;
                LDSM_X4(a[mt][0], a[mt][1], a[mt][2], a[mt][3], ad);
            }
            #pragma unroll
            for (int p = 0; p < 2; p++) {
                uint32_t bd = Bs + (rowB + p * 16) * ROWB + ks * 32 + colB;
                LDSM_X4(b[2*p][0], b[2*p][1], b[2*p+1][0], b[2*p+1][1], bd);
            }
            #pragma unroll
            for (int mt = 0; mt < 4; mt++)
                #pragma unroll
                for (int nt = 0; nt < 4; nt++)
                    MMA16816(acc[mt][nt][0], acc[mt][nt][1], acc[mt][nt][2], acc[mt][nt][3],
                             a[mt][0], a[mt][1], a[mt][2], a[mt][3],
                             b[nt][0], b[nt][1]);
        }
    }

    // epilogue: add bias, store fp32 to g_u
    #pragma unroll
    for (int nt = 0; nt < 4; nt++) {
        const long n = n0 + wn * 32 + nt * 8 + 2 * (lane & 3);
        const float2 bz = *(const float2*)&bias[n];
        #pragma unroll
        for (int mt = 0; mt < 4; mt++) {
            const long m = m0 + wm * 64 + mt * 16 + (lane >> 2);
            float2 lo = { acc[mt][nt][0] + bz.x, acc[mt][nt][1] + bz.y };
            float2 hi = { acc[mt][nt][2] + bz.x, acc[mt][nt][3] + bz.y };
            *(float2*)&g_u[(size_t)m * NTOT + n]       = lo;
            *(float2*)&g_u[(size_t)(m + 8) * NTOT + n] = hi;
        }
    }
}

// ===================== kernel 3: fused routing =====================
__device__ __forceinline__ float block_sum(float v, volatile float* smr) {
    int lane = threadIdx.x & 31, w = threadIdx.x >> 5;
    #pragma unroll
    for (int o = 16; o; o >>= 1) v += __shfl_xor_sync(0xffffffffu, v, o);
    if (lane == 0) smr[w] = v;
    __syncthreads();
    if (threadIdx.x == 0) {
        float s = smr[0];
        #pragma unroll
        for (int i = 1; i < 8; i++) s += smr[i];
        smr[8] = s;
    }
    __syncthreads();
    float r = smr[8];
    __syncthreads();
    return r;
}
__device__ __forceinline__ float block_max(float v, volatile float* smr) {
    int lane = threadIdx.x & 31, w = threadIdx.x >> 5;
    #pragma unroll
    for (int o = 16; o; o >>= 1) v = fmaxf(v, __shfl_xor_sync(0xffffffffu, v, o));
    if (lane == 0) smr[w] = v;
    __syncthreads();
    if (threadIdx.x == 0) {
        float s = smr[0];
        #pragma unroll
        for (int i = 1; i < 8; i++) s = fmaxf(s, smr[i]);
        smr[8] = s;
    }
    __syncthreads();
    float r = smr[8];
    __syncthreads();
    return r;
}

__global__ __launch_bounds__(256) void routing_kernel(float* __restrict__ out) {
    __shared__ float sred[9];
    __shared__ float s12[8 * 12];
    __shared__ float sb12[12];
    const int b = blockIdx.x;
    const int t = threadIdx.x;
    const int lid = t & 31, wid = t >> 5;

    float4 ur[12];
    const float* ub = g_u + (size_t)b * NTOT;
    #pragma unroll
    for (int c = 0; c < 12; c++)
        ur[c] = *(const float4*)(ub + c * 1024 + 4 * t);

    float blog[12];
    #pragma unroll
    for (int c = 0; c < 12; c++) blog[c] = 0.f;

    float4 s4, v4;
    for (int it = 0; it < 3; it++) {
        float mx = blog[0];
        #pragma unroll
        for (int c = 1; c < 12; c++) mx = fmaxf(mx, blog[c]);
        float cc[12], se = 0.f;
        #pragma unroll
        for (int c = 0; c < 12; c++) { cc[c] = expf(blog[c] - mx); se += cc[c]; }
        const float inv = 1.f / se;
        s4 = make_float4(0.f, 0.f, 0.f, 0.f);
        #pragma unroll
        for (int c = 0; c < 12; c++) {
            float wgt = cc[c] * inv;
            s4.x = fmaf(wgt, ur[c].x, s4.x);
            s4.y = fmaf(wgt, ur[c].y, s4.y);
            s4.z = fmaf(wgt, ur[c].z, s4.z);
            s4.w = fmaf(wgt, ur[c].w, s4.w);
        }
        float n2p = s4.x*s4.x + s4.y*s4.y + s4.z*s4.z + s4.w*s4.w;
        float n2 = block_sum(n2p, sred);
        float nrm = sqrtf(n2);
        float scale = n2 / (1.f + n2) / (nrm + 1e-8f);
        v4 = make_float4(scale*s4.x, scale*s4.y, scale*s4.z, scale*s4.w);
        if (it < 2) {
            #pragma unroll
            for (int c = 0; c < 12; c++) {
                float p = ur[c].x*v4.x + ur[c].y*v4.y + ur[c].z*v4.z + ur[c].w*v4.w;
                #pragma unroll
                for (int o = 16; o; o >>= 1) p += __shfl_xor_sync(0xffffffffu, p, o);
                if (lid == 0) s12[wid * 12 + c] = p;
            }
            __syncthreads();
            if (t < 12) {
                float a2 = 0.f;
                #pragma unroll
                for (int w2 = 0; w2 < 8; w2++) a2 += s12[w2 * 12 + t];
                sb12[t] = a2;
            }
            __syncthreads();
            #pragma unroll
            for (int c = 0; c < 12; c++) blog[c] += sb12[c];
            __syncthreads();
        }
    }

    size_t ob = (size_t)b * (A_ * DO) + 4 * t;
    #pragma unroll
    for (int a = 0; a < A_; a++)
        *(float4*)(out + ob + (size_t)a * DO) = v4;

    float mxp = fmaxf(fmaxf(s4.x, s4.y), fmaxf(s4.z, s4.w));
    float mxs = block_max(mxp, sred);
    float e0 = expf(s4.x - mxs), e1 = expf(s4.y - mxs);
    float e2 = expf(s4.z - mxs), e3 = expf(s4.w - mxs);
    float sume = block_sum(e0 + e1 + e2 + e3, sred);
    float denom = sume + 1e-10f;
    float ep = 0.f;
    {
        float p0 = e0 / denom, p1 = e1 / denom, p2 = e2 / denom, p3 = e3 / denom;
        ep += p0 * logf(p0 + 1e-10f) + p1 * logf(p1 + 1e-10f)
            + p2 * logf(p2 + 1e-10f) + p3 * logf(p3 + 1e-10f);
    }
    float H = -block_sum(ep, sred);
    H = fminf(fmaxf(H, 0.f), 10.f);
    if (t == 0) g_ent[b] = H;
}

// ===================== kernel 4: entropy loss scalar =====================
__global__ __launch_bounds__(256) void finalize_kernel(float* __restrict__ out, long idx) {
    __shared__ float sred[9];
    const int t = threadIdx.x;
    float sum = 0.f;
    for (int k = t; k < B_; k += 256) sum += g_ent[k];
    float total = block_sum(sum, sred);
    if (t == 0) {
        float mean = total / (float)B_;
        out[idx] = -0.4f / (1.f + expf(-mean));
    }
}

// ===================== launch =====================
extern "C" void kernel_launch(void* const* d_in, const int* in_sizes, int n_in,
                              void* d_out, int out_size) {
    const float* x    = (const float*)d_in[0];
    const float* W    = (const float*)d_in[1];
    const float* bias = (const float*)d_in[2];
    float* out = (float*)d_out;

    long totalq = (NX + NW) / 4;
    split_kernel<<<(int)((totalq + 255) / 256), 256>>>(x, W);

    (void)cudaFuncSetAttribute(gemm_kernel, cudaFuncAttributeMaxDynamicSharedMemorySize, GEMM_SMEM);
    dim3 ggrid(NTOT / TN, B_ / TM);   // (96, 64)
    gemm_kernel<<<ggrid, 256, GEMM_SMEM>>>(bias);

    routing_kernel<<<B_, 256>>>(out);
    finalize_kernel<<<1, 256>>>(out, (long)out_size - 1);
}